// round 1
// baseline (speedup 1.0000x reference)
#include <cuda_runtime.h>
#include <cstdint>

// Problem dims
#define BB 4
#define MM 512
#define NN 512
#define KK 128

// Decoded scratch, k-major per batch: g_dA[b][k][m], g_dB[b][k][n]
__device__ __align__(16) float g_dA[BB * KK * MM];
__device__ __align__(16) float g_dB[BB * KK * NN];

// ---------------------------------------------------------------------------
// Kernel 1: decode 8-pulse FP8 E4M3 codes -> fp32, write transposed (k-major).
// Input layout: [b][row][k][8] float pulses, MSB-first [s, e3..e0, m2..m0].
// One thread per code; reads 32B contiguous (2x float4), writes 4B scattered.
// Exact construction: power-of-two via exponent bits, mantissa (1+m/8) exact.
// ---------------------------------------------------------------------------
__global__ void decode_kernel(const float4* __restrict__ inA,
                              const float4* __restrict__ inB) {
    const int NC = BB * MM * KK;  // codes per tensor = 262144
    int idx = blockIdx.x * blockDim.x + threadIdx.x;
    if (idx >= 2 * NC) return;
    bool isB = idx >= NC;
    int i = isB ? (idx - NC) : idx;
    const float4* in = isB ? inB : inA;

    float4 p0 = in[2 * i];
    float4 p1 = in[2 * i + 1];

    // bits are exactly 0.0f / 1.0f
    float ef = p0.y * 8.0f + p0.z * 4.0f + p0.w * 2.0f + p1.x;
    float mf = p1.y * 4.0f + p1.z * 2.0f + p1.w;
    int e = (int)ef;

    float mag;
    if (e > 0) {
        // 2^(e-7) * (1 + m/8), both factors exact, product exact
        mag = __uint_as_float((unsigned)(e + 120) << 23) * (1.0f + mf * 0.125f);
    } else {
        // subnormal: m * 2^-9
        mag = mf * (1.0f / 512.0f);
    }
    float val = (p0.x > 0.5f) ? -mag : mag;

    // i = (b*512 + r)*128 + k  ->  write [b][k][r]
    int k = i & (KK - 1);
    int r = (i >> 7) & (MM - 1);
    int b = i >> 16;
    float* out = isB ? g_dB : g_dA;
    out[(b * KK + k) * MM + r] = val;
}

// ---------------------------------------------------------------------------
// Kernel 2: batched GEMM C = A @ B^T with STRICT sequential-k fp32 FMA
// accumulation (single accumulator per element, k ascending), then encode
// each fp32 result as 32 MSB-first bit planes (0.0f/1.0f) and store.
// Tile: 64x64 C per CTA, 256 threads, 4x4 register micro-tile per thread.
// ---------------------------------------------------------------------------
#define BMT 64
#define BNT 64
#define KCH 64

__global__ __launch_bounds__(256) void gemm_encode_kernel(float4* __restrict__ out) {
    __shared__ float As[KCH][BMT];  // 16 KB, k-major
    __shared__ float Bs[KCH][BNT];  // 16 KB

    const int b   = blockIdx.z;
    const int tm0 = blockIdx.y * BMT;
    const int tn0 = blockIdx.x * BNT;
    const int tid = threadIdx.x;
    const int tx  = tid & 15;   // n micro-tile selector
    const int ty  = tid >> 4;   // m micro-tile selector

    const float* __restrict__ Ab = g_dA + b * KK * MM;
    const float* __restrict__ Bb = g_dB + b * KK * NN;

    float acc[4][4];
#pragma unroll
    for (int i = 0; i < 4; i++)
#pragma unroll
        for (int j = 0; j < 4; j++) acc[i][j] = 0.0f;

#pragma unroll
    for (int k0 = 0; k0 < KK; k0 += KCH) {
        // Load 64 k-rows x 64 cols of A and B tiles (float4 coalesced).
        // 1024 float4 per tile / 256 threads = 4 each.
#pragma unroll
        for (int i = 0; i < 4; i++) {
            int r  = i * 16 + (tid >> 4);
            int c4 = (tid & 15) * 4;
            *(float4*)&As[r][c4] = *(const float4*)&Ab[(k0 + r) * MM + tm0 + c4];
            *(float4*)&Bs[r][c4] = *(const float4*)&Bb[(k0 + r) * NN + tn0 + c4];
        }
        __syncthreads();

        // Sequential over k (ascending), single accumulator per element.
#pragma unroll
        for (int k = 0; k < KCH; k++) {
            float4 a4 = *(const float4*)&As[k][ty * 4];
            float4 b4 = *(const float4*)&Bs[k][tx * 4];
            float av[4] = {a4.x, a4.y, a4.z, a4.w};
            float bv[4] = {b4.x, b4.y, b4.z, b4.w};
#pragma unroll
            for (int i = 0; i < 4; i++)
#pragma unroll
                for (int j = 0; j < 4; j++)
                    acc[i][j] = fmaf(av[i], bv[j], acc[i][j]);
        }
        __syncthreads();
    }

    // Encode + store: each C element -> 32 floats (8x float4), MSB-first.
#pragma unroll
    for (int i = 0; i < 4; i++) {
        int m = tm0 + ty * 4 + i;
#pragma unroll
        for (int j = 0; j < 4; j++) {
            int n = tn0 + tx * 4 + j;
            unsigned u = __float_as_uint(acc[i][j]);
            unsigned base = (unsigned)((b * MM + m) * NN + n) * 8u;  // float4 units
#pragma unroll
            for (int q = 0; q < 8; q++) {
                float4 v;
                v.x = (u & (1u << (31 - (q * 4 + 0)))) ? 1.0f : 0.0f;
                v.y = (u & (1u << (31 - (q * 4 + 1)))) ? 1.0f : 0.0f;
                v.z = (u & (1u << (31 - (q * 4 + 2)))) ? 1.0f : 0.0f;
                v.w = (u & (1u << (31 - (q * 4 + 3)))) ? 1.0f : 0.0f;
                out[base + q] = v;
            }
        }
    }
}

extern "C" void kernel_launch(void* const* d_in, const int* in_sizes, int n_in,
                              void* d_out, int out_size) {
    const float4* A = (const float4*)d_in[0];
    const float4* B = (const float4*)d_in[1];

    // 2 * 262144 codes / 256 threads
    decode_kernel<<<2048, 256>>>(A, B);

    dim3 grid(NN / BNT, MM / BMT, BB);  // (8, 8, 4)
    gemm_encode_kernel<<<grid, 256>>>((float4*)d_out);
}

// round 4
// speedup vs baseline: 2.0959x; 2.0959x over previous
#include <cuda_runtime.h>
#include <cstdint>

// Problem dims
#define BB 4
#define MM 512
#define NN 512
#define KK 128

// Decoded scratch, k-major per batch: g_dA[b][k][m], g_dB[b][k][n]
__device__ __align__(16) float g_dA[BB * KK * MM];
__device__ __align__(16) float g_dB[BB * KK * NN];
// fp32 GEMM result scratch: g_C[b][m][n]
__device__ __align__(16) float g_C[BB * MM * NN];

// ---------------------------------------------------------------------------
// Kernel 1: decode 8-pulse FP8 E4M3 codes -> fp32, write transposed (k-major).
// Exact construction: power-of-two via exponent-field bits; (1+m/8) exact.
// ---------------------------------------------------------------------------
__global__ void decode_kernel(const float4* __restrict__ inA,
                              const float4* __restrict__ inB) {
    const int NC = BB * MM * KK;  // 262144 codes per tensor
    int idx = blockIdx.x * blockDim.x + threadIdx.x;
    if (idx >= 2 * NC) return;
    bool isB = idx >= NC;
    int i = isB ? (idx - NC) : idx;
    const float4* in = isB ? inB : inA;

    float4 p0 = in[2 * i];
    float4 p1 = in[2 * i + 1];

    float ef = p0.y * 8.0f + p0.z * 4.0f + p0.w * 2.0f + p1.x;
    float mf = p1.y * 4.0f + p1.z * 2.0f + p1.w;
    int e = (int)ef;

    float mag;
    if (e > 0) {
        mag = __uint_as_float((unsigned)(e + 120) << 23) * (1.0f + mf * 0.125f);
    } else {
        mag = mf * (1.0f / 512.0f);  // subnormal: m * 2^-9
    }
    float val = (p0.x > 0.5f) ? -mag : mag;

    int k = i & (KK - 1);
    int r = (i >> 7) & (MM - 1);
    int b = i >> 16;
    float* out = isB ? g_dB : g_dA;
    out[(b * KK + k) * MM + r] = val;
}

// ---------------------------------------------------------------------------
// Kernel 2: batched GEMM C = A @ B^T with STRICT sequential-k fp32 FMA
// accumulation (single accumulator per element, k ascending). Writes plain
// fp32 C to scratch, coalesced.
// ---------------------------------------------------------------------------
#define BMT 64
#define BNT 64
#define KCH 64

__global__ __launch_bounds__(256) void gemm_kernel() {
    __shared__ float As[KCH][BMT];
    __shared__ float Bs[KCH][BNT];

    const int b   = blockIdx.z;
    const int tm0 = blockIdx.y * BMT;
    const int tn0 = blockIdx.x * BNT;
    const int tid = threadIdx.x;
    const int tx  = tid & 15;
    const int ty  = tid >> 4;

    const float* __restrict__ Ab = g_dA + b * KK * MM;
    const float* __restrict__ Bb = g_dB + b * KK * NN;

    float acc[4][4];
#pragma unroll
    for (int i = 0; i < 4; i++)
#pragma unroll
        for (int j = 0; j < 4; j++) acc[i][j] = 0.0f;

#pragma unroll
    for (int k0 = 0; k0 < KK; k0 += KCH) {
#pragma unroll
        for (int i = 0; i < 4; i++) {
            int r  = i * 16 + (tid >> 4);
            int c4 = (tid & 15) * 4;
            *(float4*)&As[r][c4] = *(const float4*)&Ab[(k0 + r) * MM + tm0 + c4];
            *(float4*)&Bs[r][c4] = *(const float4*)&Bb[(k0 + r) * NN + tn0 + c4];
        }
        __syncthreads();

        // Sequential over k (ascending), single accumulator per element.
        // DO NOT reassociate: bit-exactness vs reference depends on this.
#pragma unroll
        for (int k = 0; k < KCH; k++) {
            float4 a4 = *(const float4*)&As[k][ty * 4];
            float4 b4 = *(const float4*)&Bs[k][tx * 4];
            float av[4] = {a4.x, a4.y, a4.z, a4.w};
            float bv[4] = {b4.x, b4.y, b4.z, b4.w};
#pragma unroll
            for (int i = 0; i < 4; i++)
#pragma unroll
                for (int j = 0; j < 4; j++)
                    acc[i][j] = fmaf(av[i], bv[j], acc[i][j]);
        }
        __syncthreads();
    }

    // Store C tile, coalesced (consecutive tx -> consecutive 16B).
#pragma unroll
    for (int i = 0; i < 4; i++) {
        int m = tm0 + ty * 4 + i;
        float4 v = make_float4(acc[i][0], acc[i][1], acc[i][2], acc[i][3]);
        *(float4*)&g_C[(b * MM + m) * NN + tn0 + tx * 4] = v;
    }
}

// ---------------------------------------------------------------------------
// Kernel 3: encode expand. One thread per output float4 (4 bit planes).
// Warp writes 512B contiguous per STG.128; 8 adjacent lanes share one C value
// (L1 broadcast). Pure streaming: read 4MB (L2-hot), write 128MB.
// ---------------------------------------------------------------------------
__global__ __launch_bounds__(256) void encode_kernel(float4* __restrict__ out,
                                                     unsigned n4) {
    unsigned t = blockIdx.x * 256u + threadIdx.x;  // output float4 index
    if (t >= n4) return;
    unsigned u = __float_as_uint(__ldg(&g_C[t >> 3]));
    unsigned q = t & 7u;
    unsigned s = 28u - 4u * q;  // v.w bit position
    float4 v;
    v.x = ((u >> (s + 3)) & 1u) ? 1.0f : 0.0f;
    v.y = ((u >> (s + 2)) & 1u) ? 1.0f : 0.0f;
    v.z = ((u >> (s + 1)) & 1u) ? 1.0f : 0.0f;
    v.w = ((u >> s) & 1u) ? 1.0f : 0.0f;
    out[t] = v;
}

extern "C" void kernel_launch(void* const* d_in, const int* in_sizes, int n_in,
                              void* d_out, int out_size) {
    const float4* A = (const float4*)d_in[0];
    const float4* B = (const float4*)d_in[1];

    decode_kernel<<<2048, 256>>>(A, B);

    dim3 grid(NN / BNT, MM / BMT, BB);  // (8, 8, 4)
    gemm_kernel<<<grid, 256>>>();

    unsigned n4 = (unsigned)(out_size / 4);  // 8388608 float4s
    encode_kernel<<<(n4 + 255) / 256, 256>>>((float4*)d_out, n4);
}

// round 5
// speedup vs baseline: 2.1896x; 1.0447x over previous
#include <cuda_runtime.h>
#include <cstdint>

// Problem dims
#define BB 4
#define MM 512
#define NN 512
#define KK 128

// Decoded scratch, k-major per batch: g_dA[b][k][m], g_dB[b][k][n]
__device__ __align__(16) float g_dA[BB * KK * MM];
__device__ __align__(16) float g_dB[BB * KK * NN];
// fp32 GEMM result scratch: g_C[b][m][n]
__device__ __align__(16) float g_C[BB * MM * NN];

// ---------------------------------------------------------------------------
// Kernel 1: decode 8-pulse FP8 E4M3 codes -> fp32, k-major output, with a
// shared-memory transpose so BOTH input reads and output writes are fully
// coalesced (float4 stores, 4 full 128B lines per warp store).
// CTA: 32 rows x 128 k of one (matrix, batch) = 4096 codes, 128KB input.
// Grid: 2 matrices * 4 batches * 16 row-blocks = 128 CTAs (one wave).
// Exact decode: power-of-two via exponent field; (1+m/8) exact.
// ---------------------------------------------------------------------------
#define DEC_R 32

__global__ __launch_bounds__(256) void decode_kernel(const float4* __restrict__ inA,
                                                     const float4* __restrict__ inB) {
    __shared__ float s[KK][DEC_R + 1];  // pad -> conflict-free

    const int blk = blockIdx.x;          // 0..127
    const bool isB = blk >= 64;
    const int sub = isB ? (blk - 64) : blk;   // 0..63
    const int b  = sub >> 4;             // batch
    const int r0 = (sub & 15) * DEC_R;   // row-block start

    const float4* __restrict__ in = isB ? inB : inA;
    float* __restrict__ outp = isB ? g_dB : g_dA;

    const int tid = threadIdx.x;
    // global code base for this block: codes are [b][row][k] contiguous
    const long gbase = ((long)(b * MM + r0)) * KK;

    // Decode 16 codes per thread; input fully coalesced (32B per code).
#pragma unroll
    for (int j = 0; j < 16; j++) {
        int c = j * 256 + tid;           // 0..4095: r_local = c>>7, k = c&127
        float4 p0 = in[(gbase + c) * 2];
        float4 p1 = in[(gbase + c) * 2 + 1];

        float ef = p0.y * 8.0f + p0.z * 4.0f + p0.w * 2.0f + p1.x;
        float mf = p1.y * 4.0f + p1.z * 2.0f + p1.w;
        int e = (int)ef;

        float mag;
        if (e > 0) {
            mag = __uint_as_float((unsigned)(e + 120) << 23) * (1.0f + mf * 0.125f);
        } else {
            mag = mf * (1.0f / 512.0f);  // subnormal: m * 2^-9
        }
        float val = (p0.x > 0.5f) ? -mag : mag;

        s[c & (KK - 1)][c >> 7] = val;
    }
    __syncthreads();

    // Write k-major: out[(b*128 + k)*512 + r0 + r], float4 over r.
    // 128 k * 8 float4 = 1024 float4 / 256 threads = 4 each.
#pragma unroll
    for (int j = 0; j < 4; j++) {
        int w  = j * 256 + tid;          // 0..1023
        int k  = w >> 3;
        int r4 = (w & 7) * 4;
        float4 v;
        v.x = s[k][r4 + 0];
        v.y = s[k][r4 + 1];
        v.z = s[k][r4 + 2];
        v.w = s[k][r4 + 3];
        *(float4*)&outp[(b * KK + k) * MM + r0 + r4] = v;
    }
}

// ---------------------------------------------------------------------------
// Kernel 2: batched GEMM C = A @ B^T with STRICT sequential-k fp32 FMA
// accumulation (single accumulator per element, k ascending). Writes plain
// fp32 C to scratch, coalesced. DO NOT reassociate (bit-exactness).
// ---------------------------------------------------------------------------
#define BMT 64
#define BNT 64
#define KCH 64

__global__ __launch_bounds__(256) void gemm_kernel() {
    __shared__ float As[KCH][BMT];
    __shared__ float Bs[KCH][BNT];

    const int b   = blockIdx.z;
    const int tm0 = blockIdx.y * BMT;
    const int tn0 = blockIdx.x * BNT;
    const int tid = threadIdx.x;
    const int tx  = tid & 15;
    const int ty  = tid >> 4;

    const float* __restrict__ Ab = g_dA + b * KK * MM;
    const float* __restrict__ Bb = g_dB + b * KK * NN;

    float acc[4][4];
#pragma unroll
    for (int i = 0; i < 4; i++)
#pragma unroll
        for (int j = 0; j < 4; j++) acc[i][j] = 0.0f;

#pragma unroll
    for (int k0 = 0; k0 < KK; k0 += KCH) {
#pragma unroll
        for (int i = 0; i < 4; i++) {
            int r  = i * 16 + (tid >> 4);
            int c4 = (tid & 15) * 4;
            *(float4*)&As[r][c4] = *(const float4*)&Ab[(k0 + r) * MM + tm0 + c4];
            *(float4*)&Bs[r][c4] = *(const float4*)&Bb[(k0 + r) * NN + tn0 + c4];
        }
        __syncthreads();

#pragma unroll
        for (int k = 0; k < KCH; k++) {
            float4 a4 = *(const float4*)&As[k][ty * 4];
            float4 b4 = *(const float4*)&Bs[k][tx * 4];
            float av[4] = {a4.x, a4.y, a4.z, a4.w};
            float bv[4] = {b4.x, b4.y, b4.z, b4.w};
#pragma unroll
            for (int i = 0; i < 4; i++)
#pragma unroll
                for (int j = 0; j < 4; j++)
                    acc[i][j] = fmaf(av[i], bv[j], acc[i][j]);
        }
        __syncthreads();
    }

#pragma unroll
    for (int i = 0; i < 4; i++) {
        int m = tm0 + ty * 4 + i;
        float4 v = make_float4(acc[i][0], acc[i][1], acc[i][2], acc[i][3]);
        *(float4*)&g_C[(b * MM + m) * NN + tn0 + tx * 4] = v;
    }
}

// ---------------------------------------------------------------------------
// Kernel 3: encode expand. One thread per TWO consecutive output float4s
// (8 bit planes = one C element read per thread). Warp writes 1KB contiguous
// per pair of STG.128. Streaming stores (.cs) keep C L2-resident.
// ---------------------------------------------------------------------------
__global__ __launch_bounds__(256) void encode_kernel(float4* __restrict__ out,
                                                     unsigned n2) {
    unsigned t = blockIdx.x * 256u + threadIdx.x;  // pair index, 0..n2-1
    if (t >= n2) return;
    unsigned u = __float_as_uint(__ldg(&g_C[t >> 2]));
    unsigned q = (t & 3u) * 2u;        // first nibble index of the pair
    unsigned s0 = 28u - 4u * q;        // bit pos of .w of first float4
    float4 v0, v1;
    v0.x = ((u >> (s0 + 3)) & 1u) ? 1.0f : 0.0f;
    v0.y = ((u >> (s0 + 2)) & 1u) ? 1.0f : 0.0f;
    v0.z = ((u >> (s0 + 1)) & 1u) ? 1.0f : 0.0f;
    v0.w = ((u >> (s0 + 0)) & 1u) ? 1.0f : 0.0f;
    unsigned s1 = s0 - 4u;
    v1.x = ((u >> (s1 + 3)) & 1u) ? 1.0f : 0.0f;
    v1.y = ((u >> (s1 + 2)) & 1u) ? 1.0f : 0.0f;
    v1.z = ((u >> (s1 + 1)) & 1u) ? 1.0f : 0.0f;
    v1.w = ((u >> (s1 + 0)) & 1u) ? 1.0f : 0.0f;
    __stcs(&out[2 * t], v0);
    __stcs(&out[2 * t + 1], v1);
}

extern "C" void kernel_launch(void* const* d_in, const int* in_sizes, int n_in,
                              void* d_out, int out_size) {
    const float4* A = (const float4*)d_in[0];
    const float4* B = (const float4*)d_in[1];

    decode_kernel<<<128, 256>>>(A, B);

    dim3 grid(NN / BNT, MM / BMT, BB);  // (8, 8, 4)
    gemm_kernel<<<grid, 256>>>();

    unsigned n2 = (unsigned)(out_size / 8);  // float4 pairs: 4194304
    encode_kernel<<<(n2 + 255) / 256, 256>>>((float4*)d_out, n2);
}